// round 13
// baseline (speedup 1.0000x reference)
#include <cuda_runtime.h>
#include <cuda_bf16.h>
#include <cstdint>

// Problem constants
#define BATCH    16384
#define IN_SIZE  448
#define OUT_SIZE 448
#define W_TOT    14336
#define NE       64
#define NB       128
#define NTHREADS 512
#define PTHREADS 256
#define NHB      (BATCH / PTHREADS)   // 64
#define MAX_TILES 192
#define GRID_COMPUTE 148

// B (W^T) image layout per element, padded row strides (odd*16 -> conflict-free)
#define B0_STR 208
#define B1_STR 144
#define B2_STR 80
#define OFF_B0H 0
#define OFF_B0L 19968
#define OFF_B1H 39936
#define OFF_B1L 49152
#define OFF_B2H 58368
#define OFF_B2L 60928
#define IMG_BYTES 63488

// Per-node blob (R10-verified layout): s0h@0(208) s0l@208(208)
// s1 m: h@416+288m(144) l@+144 ; s2 m: h@1280+160m(80) l@+80 ; total 2080
#define XN_BYTES 2080
#define XOFF_S0H 0
#define XOFF_S0L 208
#define XOFF_S1(m) (416 + 288 * (m))
#define XOFF_S2(m) (1280 + 160 * (m))

__device__ unsigned char g_Wimg[(size_t)NE * IMG_BYTES];
__device__ unsigned char g_xre[(size_t)BATCH * XN_BYTES];
__device__ int g_hist[NHB][NE];
__device__ int g_perm[BATCH];
__device__ int g_ntiles;
__device__ int g_tile_ctr;
__device__ int g_tile_e[MAX_TILES];
__device__ int g_tile_r0[MAX_TILES];
__device__ int g_tile_R[MAX_TILES];

__device__ __forceinline__ int get_idx(const void* p, int b, int is64) {
    if (is64) return (int)((const long long*)p)[b];
    return ((const int*)p)[b];
}
__device__ __forceinline__ int detect_is64(const void* idxp, int tid, int* s_flag) {
    if (tid < 32) {
        long long v = ((const long long*)idxp)[tid];
        unsigned ok = __ballot_sync(0xFFFFFFFFu, v >= 0 && v < 64);
        if (tid == 0) *s_flag = (ok == 0xFFFFFFFFu) ? 1 : 0;
    }
    __syncthreads();
    return *s_flag;
}
__device__ __forceinline__ uint32_t pk2(float a, float b, float* la, float* lb) {
    __nv_bfloat16 ha = __float2bfloat16_rn(a);
    __nv_bfloat16 hb = __float2bfloat16_rn(b);
    *la = a - __bfloat162float(ha);
    *lb = b - __bfloat162float(hb);
    uint16_t ua, ub;
    memcpy(&ua, &ha, 2); memcpy(&ub, &hb, 2);
    return (uint32_t)ua | ((uint32_t)ub << 16);
}
__device__ __forceinline__ uint32_t pk2lo(float la, float lb) {
    __nv_bfloat16 a = __float2bfloat16_rn(la);
    __nv_bfloat16 b = __float2bfloat16_rn(lb);
    uint16_t ua, ub;
    memcpy(&ua, &a, 2); memcpy(&ub, &b, 2);
    return (uint32_t)ua | ((uint32_t)ub << 16);
}

// ---------------------------------------------------------------------------
// K0: fused prep.
//   blocks [0,128):        W images (2 blocks per element)
//   blocks [128,192):      histogram
//   blocks [192,192+2048): xconv v2 (8 nodes per block, coalesced in/out)
// ---------------------------------------------------------------------------
#define XC_NODES 8
#define XC_BLOCKS (BATCH / XC_NODES)   // 2048
__global__ void prep_kernel(const float* __restrict__ W,
                            const float* __restrict__ x, const void* idxp) {
    __shared__ float sx[XC_NODES * IN_SIZE];            // 14336 B
    __shared__ unsigned char sblob[XC_NODES * XN_BYTES];// 16640 B
    int tid = threadIdx.x;
    int blk = blockIdx.x;

    if (blk < 128) {
        // ---- W image: element e = blk/2, half = blk&1 handles o-range half
        int e = blk >> 1, hf = blk & 1;
        const float* We = W + (size_t)e * W_TOT;
        unsigned char* img = g_Wimg + (size_t)e * IMG_BYTES;
        // seg0: o in [48*hf, 48*hf+48)
        for (int i = tid; i < 48 * 48; i += PTHREADS) {
            int o = 48 * hf + i / 48, k = 2 * (i % 48);
            float la, lb;
            uint32_t h = pk2(We[k * 96 + o], We[(k + 1) * 96 + o], &la, &lb);
            *(uint32_t*)(img + OFF_B0H + o * B0_STR + 2 * k) = h;
            *(uint32_t*)(img + OFF_B0L + o * B0_STR + 2 * k) = pk2lo(la, lb);
        }
        // seg1: o in [32*hf, +32)
        for (int i = tid; i < 32 * 32; i += PTHREADS) {
            int o = 32 * hf + (i >> 5), k = (i & 31) * 2;
            float la, lb;
            uint32_t h = pk2(We[9216 + k * 64 + o], We[9216 + (k + 1) * 64 + o], &la, &lb);
            *(uint32_t*)(img + OFF_B1H + o * B1_STR + 2 * k) = h;
            *(uint32_t*)(img + OFF_B1L + o * B1_STR + 2 * k) = pk2lo(la, lb);
        }
        // seg2: o in [16*hf, +16)
        for (int i = tid; i < 16 * 16; i += PTHREADS) {
            int o = 16 * hf + (i >> 4), k = (i & 15) * 2;
            float la, lb;
            uint32_t h = pk2(We[13312 + k * 32 + o], We[13312 + (k + 1) * 32 + o], &la, &lb);
            *(uint32_t*)(img + OFF_B2H + o * B2_STR + 2 * k) = h;
            *(uint32_t*)(img + OFF_B2L + o * B2_STR + 2 * k) = pk2lo(la, lb);
        }
    } else if (blk < 192) {
        // ---- histogram
        __shared__ int h[NE];
        __shared__ int sflag;
        int b = blk - 128;
        if (tid < NE) h[tid] = 0;
        int is64 = detect_is64(idxp, tid, &sflag);
        int e = get_idx(idxp, b * PTHREADS + tid, is64);
        atomicAdd(&h[e], 1);
        __syncthreads();
        if (tid < NE) g_hist[b][tid] = h[tid];
    } else {
        // ---- xconv v2
        int nb0 = (blk - 192) * XC_NODES;
        // coalesced load: 8 nodes x 112 float4
        for (int i = tid; i < XC_NODES * 112; i += PTHREADS) {
            int n = i / 112, q = i - 112 * n;
            *(float4*)&sx[n * IN_SIZE + 4 * q] =
                *(const float4*)(x + (size_t)(nb0 + n) * IN_SIZE + 4 * q);
        }
        __syncthreads();
        // convert 224 hi/lo u32-pairs per node into blob
        for (int i = tid; i < XC_NODES * 224; i += PTHREADS) {
            int n = i / 224, r = i - 224 * n;
            const float* row = sx + n * IN_SIZE;
            unsigned char* ob = sblob + n * XN_BYTES;
            float a, b2;
            int hoff, loff, j;
            if (r < 48) {                       // seg0, pair j -> k=2j
                j = r;
                a = row[2 * j]; b2 = row[2 * j + 1];
                hoff = XOFF_S0H; loff = XOFF_S0L;
            } else if (r < 144) {               // seg1: m, j (k=2j)
                int rr = r - 48, m = rr >> 5;
                j = rr & 31;
                int k = 2 * j;
                a = row[96 + 3 * k + m]; b2 = row[96 + 3 * (k + 1) + m];
                hoff = XOFF_S1(m); loff = hoff + 144;
            } else {                            // seg2: m, j (k=2j)
                int rr = r - 144, m = rr >> 4;
                j = rr & 15;
                int k = 2 * j;
                a = row[288 + 5 * k + m]; b2 = row[288 + 5 * (k + 1) + m];
                hoff = XOFF_S2(m); loff = hoff + 80;
            }
            float la, lb;
            uint32_t h = pk2(a, b2, &la, &lb);
            *(uint32_t*)(ob + hoff + 4 * j) = h;
            *(uint32_t*)(ob + loff + 4 * j) = pk2lo(la, lb);
        }
        __syncthreads();
        // coalesced 16B write-out of blobs
        unsigned char* dst = g_xre + (size_t)nb0 * XN_BYTES;
        for (int i = tid; i < XC_NODES * XN_BYTES / 16; i += PTHREADS)
            *(float4*)(dst + 16 * i) = *(const float4*)(sblob + 16 * i);
    }
}

// ---------------------------------------------------------------------------
// K1: fused scan + scatter + tile-list (NB=128 tiles, full first)
// ---------------------------------------------------------------------------
__global__ void finish_kernel(const void* idxp) {
    __shared__ int preS[NE], totS[NE], offS[NE];
    __shared__ int sflag;
    int t = threadIdx.x, b = blockIdx.x;
    int is64 = detect_is64(idxp, t, &sflag);
    if (t < NE) {
        int pre = 0, tot = 0;
        #pragma unroll 8
        for (int bb = 0; bb < NHB; bb++) {
            int v = g_hist[bb][t];
            tot += v;
            if (bb < b) pre += v;
        }
        preS[t] = pre; totS[t] = tot;
    }
    __syncthreads();
    if (t == 0) {
        int s = 0;
        for (int e2 = 0; e2 < NE; e2++) { offS[e2] = s; s += totS[e2]; }
    }
    __syncthreads();
    int my = b * PTHREADS + t;
    int e = get_idx(idxp, my, is64);
    int rank = atomicAdd(&preS[e], 1);
    g_perm[offS[e] + rank] = my;

    if (b == 0 && t == 0) {
        int ts = 0;
        for (int e2 = 0; e2 < NE; e2++) {
            int c = totS[e2], o = offS[e2], nf = c >> 7;
            for (int i = 0; i < nf; i++) {
                g_tile_e[ts] = e2; g_tile_r0[ts] = o + (i << 7); g_tile_R[ts] = NB; ts++;
            }
        }
        for (int e2 = 0; e2 < NE; e2++) {
            int c = totS[e2], o = offS[e2], nf = c >> 7, rem = c & 127;
            if (rem) {
                g_tile_e[ts] = e2; g_tile_r0[ts] = o + (nf << 7); g_tile_R[ts] = rem; ts++;
            }
        }
        g_ntiles = ts;
        g_tile_ctr = 0;
    }
}

// ---------------------------------------------------------------------------
// Compute: HMMA bf16 3-term split (verified core), double-buffered A pipeline
// SMEM: ctrl 1024 | A ring 2x36864 | B images 63488 = 138240
// ---------------------------------------------------------------------------
#define A_OFF  1024
#define A_HALF 36864
#define BB_OFF (1024 + 2 * A_HALF)
#define SMEM_BYTES (1024 + 2 * A_HALF + 63488)

__device__ __forceinline__ uint32_t smem_u32(const void* p) {
    uint32_t a;
    asm("{ .reg .u64 t; cvta.to.shared.u64 t, %1; cvt.u32.u64 %0, t; }"
        : "=r"(a) : "l"(p));
    return a;
}
__device__ __forceinline__ void cpa16(uint32_t dst, const void* src) {
    asm volatile("cp.async.cg.shared.global [%0], [%1], 16;\n" :: "r"(dst), "l"(src));
}
__device__ __forceinline__ void cpa_commit() {
    asm volatile("cp.async.commit_group;\n" ::: "memory");
}
__device__ __forceinline__ void cpa_wait0() {
    asm volatile("cp.async.wait_group 0;\n" ::: "memory");
}
__device__ __forceinline__ void ldm4(uint32_t* r, uint32_t a) {
    asm volatile("ldmatrix.sync.aligned.m8n8.x4.shared.b16 {%0,%1,%2,%3}, [%4];"
                 : "=r"(r[0]), "=r"(r[1]), "=r"(r[2]), "=r"(r[3]) : "r"(a));
}
__device__ __forceinline__ void mma16816(float* d, const uint32_t* a, const uint32_t* b) {
    asm volatile(
        "mma.sync.aligned.m16n8k16.row.col.f32.bf16.bf16.f32 "
        "{%0,%1,%2,%3}, {%4,%5,%6,%7}, {%8,%9}, {%0,%1,%2,%3};"
        : "+f"(d[0]), "+f"(d[1]), "+f"(d[2]), "+f"(d[3])
        : "r"(a[0]), "r"(a[1]), "r"(a[2]), "r"(a[3]), "r"(b[0]), "r"(b[1]));
}

// Stage A for pipeline phase p (p<3: seg1 m=p; else seg2 m=p-3) into buf.
__device__ __forceinline__ void stage_phase(int p, uint32_t buf, int R, int tid,
                                            const int* s_node) {
    if (p < 3) {
        int m = p;
        for (int i = tid; i < R * 18; i += NTHREADS) {
            int nb = i / 18, j = i - 18 * nb;
            const unsigned char* src = g_xre + (size_t)s_node[nb] * XN_BYTES + XOFF_S1(m);
            if (j < 9) cpa16(buf + nb * B1_STR + 16 * j, src + 16 * j);
            else cpa16(buf + 18432 + nb * B1_STR + 16 * (j - 9), src + 144 + 16 * (j - 9));
        }
    } else {
        int m = p - 3;
        for (int i = tid; i < R * 10; i += NTHREADS) {
            int nb = i / 10, j = i - 10 * nb;
            const unsigned char* src = g_xre + (size_t)s_node[nb] * XN_BYTES + XOFF_S2(m);
            if (j < 5) cpa16(buf + nb * B2_STR + 16 * j, src + 16 * j);
            else cpa16(buf + 10240 + nb * B2_STR + 16 * (j - 5), src + 80 + 16 * (j - 5));
        }
    }
    cpa_commit();
}

__global__ void __launch_bounds__(NTHREADS)
compute_kernel(float* __restrict__ y)
{
    extern __shared__ unsigned char sm[];
    int* s_tile = (int*)(sm);
    int* s_node = (int*)(sm + 16);

    const int tid = threadIdx.x, lane = tid & 31, wid = tid >> 5;
    const int wr = wid & 7, wc = wid >> 3;        // 8 row stripes x 2 col halves
    const uint32_t base_u = smem_u32(sm);
    const uint32_t sA = base_u + A_OFF;
    const uint32_t sB = base_u + BB_OFF;
    const int nt = g_ntiles;

    // verified ldmatrix lane components (R10/R11/R12, rel_err 4.45e-6)
    const int a_row = lane & 15;
    const int a_k16 = (lane >> 4) << 4;
    const int b_row = (lane & 7) + ((lane >> 4) << 3);
    const int b_k16 = ((lane >> 3) & 1) << 4;

    for (int iter = 0; iter < 8; iter++) {
        if (tid == 0) *s_tile = atomicAdd(&g_tile_ctr, 1);
        __syncthreads();
        const int t = *s_tile;
        if (t >= nt) break;
        const int e  = g_tile_e[t];
        const int r0 = g_tile_r0[t];
        const int R  = g_tile_R[t];
        if (tid < NB) s_node[tid] = g_perm[r0 + min(tid, R - 1)];
        __syncthreads();

        // Stage B images + seg0 A (hi/lo across both halves of the A ring)
        {
            const unsigned char* bs = g_Wimg + (size_t)e * IMG_BYTES;
            for (int i = tid; i < IMG_BYTES / 16; i += NTHREADS)
                cpa16(sB + 16u * i, bs + 16 * i);
            for (int i = tid; i < R * 26; i += NTHREADS) {
                int nb = i / 26, j = i - 26 * nb;
                const unsigned char* src = g_xre + (size_t)s_node[nb] * XN_BYTES;
                if (j < 13) cpa16(sA + nb * B0_STR + 16 * j, src + 16 * j);
                else cpa16(sA + 26624 + nb * B0_STR + 16 * (j - 13), src + 208 + 16 * (j - 13));
            }
            cpa_commit(); cpa_wait0();
        }
        __syncthreads();

        // ===== seg0: M=128 N=96 K=96 (verified) =====
        if (16 * wr < R) {
            float c[6][4];
            #pragma unroll
            for (int j = 0; j < 6; j++)
                #pragma unroll
                for (int q = 0; q < 4; q++) c[j][q] = 0.f;
            const uint32_t ah = sA + (16 * wr + a_row) * B0_STR + a_k16;
            const uint32_t al = ah + 26624;
            const uint32_t bh = sB + OFF_B0H + (48 * wc + b_row) * B0_STR + b_k16;
            const uint32_t bl = sB + OFF_B0L + (48 * wc + b_row) * B0_STR + b_k16;
            #pragma unroll
            for (int kk = 0; kk < 6; kk++) {
                uint32_t A[4], Al[4];
                ldm4(A, ah + 32 * kk);
                ldm4(Al, al + 32 * kk);
                #pragma unroll
                for (int p = 0; p < 3; p++) {
                    uint32_t Bh[4], Bl[4];
                    ldm4(Bh, bh + p * (16 * B0_STR) + 32 * kk);
                    ldm4(Bl, bl + p * (16 * B0_STR) + 32 * kk);
                    mma16816(c[2 * p], A, Bh);
                    mma16816(c[2 * p], Al, Bh);
                    mma16816(c[2 * p], A, Bl);
                    mma16816(c[2 * p + 1], A, Bh + 2);
                    mma16816(c[2 * p + 1], Al, Bh + 2);
                    mma16816(c[2 * p + 1], A, Bl + 2);
                }
            }
            int rA = 16 * wr + (lane >> 2), rB = rA + 8;
            int cb = 48 * wc + 2 * (lane & 3);
            if (rA < R) {
                float* yp = y + (size_t)s_node[rA] * OUT_SIZE;
                #pragma unroll
                for (int j = 0; j < 6; j++)
                    *(float2*)(yp + cb + 8 * j) = make_float2(c[j][0], c[j][1]);
            }
            if (rB < R) {
                float* yp = y + (size_t)s_node[rB] * OUT_SIZE;
                #pragma unroll
                for (int j = 0; j < 6; j++)
                    *(float2*)(yp + cb + 8 * j) = make_float2(c[j][2], c[j][3]);
            }
        }
        __syncthreads();   // seg0 A reads done -> ring reusable

        // ===== pipelined phases p=0..7: s1m0..2, s2m0..4 =====
        stage_phase(0, sA + 0, R, tid, s_node);
        cpa_wait0();
        __syncthreads();
        for (int p = 0; p < 8; p++) {
            if (p < 7)   // prefetch next phase into other half
                stage_phase(p + 1, sA + ((p + 1) & 1) * A_HALF, R, tid, s_node);
            const uint32_t buf = sA + (p & 1) * A_HALF;
            if (p < 3) {
                // seg1 m=p: M=128 N=64 K=64 (verified math, re-based)
                const int m = p;
                if (16 * wr < R) {
                    float c[4][4];
                    #pragma unroll
                    for (int j = 0; j < 4; j++)
                        #pragma unroll
                        for (int q = 0; q < 4; q++) c[j][q] = 0.f;
                    const uint32_t ah = buf + (16 * wr + a_row) * B1_STR + a_k16;
                    const uint32_t al = ah + 18432;
                    const uint32_t bh = sB + OFF_B1H + (32 * wc + b_row) * B1_STR + b_k16;
                    const uint32_t bl = sB + OFF_B1L + (32 * wc + b_row) * B1_STR + b_k16;
                    #pragma unroll
                    for (int kk = 0; kk < 4; kk++) {
                        uint32_t A[4], Al[4];
                        ldm4(A, ah + 32 * kk);
                        ldm4(Al, al + 32 * kk);
                        #pragma unroll
                        for (int pp = 0; pp < 2; pp++) {
                            uint32_t Bh[4], Bl[4];
                            ldm4(Bh, bh + pp * (16 * B1_STR) + 32 * kk);
                            ldm4(Bl, bl + pp * (16 * B1_STR) + 32 * kk);
                            mma16816(c[2 * pp], A, Bh);
                            mma16816(c[2 * pp], Al, Bh);
                            mma16816(c[2 * pp], A, Bl);
                            mma16816(c[2 * pp + 1], A, Bh + 2);
                            mma16816(c[2 * pp + 1], Al, Bh + 2);
                            mma16816(c[2 * pp + 1], A, Bl + 2);
                        }
                    }
                    int rA = 16 * wr + (lane >> 2), rB = rA + 8;
                    int cb = 32 * wc + 2 * (lane & 3);
                    if (rA < R) {
                        float* yp = y + (size_t)s_node[rA] * OUT_SIZE + 96 + m;
                        #pragma unroll
                        for (int j = 0; j < 4; j++) {
                            yp[3 * (cb + 8 * j)] = c[j][0];
                            yp[3 * (cb + 8 * j + 1)] = c[j][1];
                        }
                    }
                    if (rB < R) {
                        float* yp = y + (size_t)s_node[rB] * OUT_SIZE + 96 + m;
                        #pragma unroll
                        for (int j = 0; j < 4; j++) {
                            yp[3 * (cb + 8 * j)] = c[j][2];
                            yp[3 * (cb + 8 * j + 1)] = c[j][3];
                        }
                    }
                }
            } else {
                // seg2 m=p-3: M=128 N=32 K=32 (verified math, re-based)
                const int m = p - 3;
                if (16 * wr < R) {
                    float c[2][4];
                    #pragma unroll
                    for (int j = 0; j < 2; j++)
                        #pragma unroll
                        for (int q = 0; q < 4; q++) c[j][q] = 0.f;
                    const uint32_t ah = buf + (16 * wr + a_row) * B2_STR + a_k16;
                    const uint32_t al = ah + 10240;
                    const uint32_t bh = sB + OFF_B2H + (16 * wc + b_row) * B2_STR + b_k16;
                    const uint32_t bl = sB + OFF_B2L + (16 * wc + b_row) * B2_STR + b_k16;
                    #pragma unroll
                    for (int kk = 0; kk < 2; kk++) {
                        uint32_t A[4], Al[4], Bh[4], Bl[4];
                        ldm4(A, ah + 32 * kk);
                        ldm4(Al, al + 32 * kk);
                        ldm4(Bh, bh + 32 * kk);
                        ldm4(Bl, bl + 32 * kk);
                        mma16816(c[0], A, Bh);
                        mma16816(c[0], Al, Bh);
                        mma16816(c[0], A, Bl);
                        mma16816(c[1], A, Bh + 2);
                        mma16816(c[1], Al, Bh + 2);
                        mma16816(c[1], A, Bl + 2);
                    }
                    int rA = 16 * wr + (lane >> 2), rB = rA + 8;
                    int cb = 16 * wc + 2 * (lane & 3);
                    if (rA < R) {
                        float* yp = y + (size_t)s_node[rA] * OUT_SIZE + 288 + m;
                        #pragma unroll
                        for (int j = 0; j < 2; j++) {
                            yp[5 * (cb + 8 * j)] = c[j][0];
                            yp[5 * (cb + 8 * j + 1)] = c[j][1];
                        }
                    }
                    if (rB < R) {
                        float* yp = y + (size_t)s_node[rB] * OUT_SIZE + 288 + m;
                        #pragma unroll
                        for (int j = 0; j < 2; j++) {
                            yp[5 * (cb + 8 * j)] = c[j][2];
                            yp[5 * (cb + 8 * j + 1)] = c[j][3];
                        }
                    }
                }
            }
            cpa_wait0();       // next-phase staging landed
            __syncthreads();   // all reads of buf[p&1] done before p+2 overwrite
        }
    }
}

// ---------------------------------------------------------------------------
// Launch (3 kernels)
// ---------------------------------------------------------------------------
extern "C" void kernel_launch(void* const* d_in, const int* in_sizes, int n_in,
                              void* d_out, int out_size)
{
    const float* W  = (const float*)d_in[0];   // [64, 14336]
    const float* x  = (const float*)d_in[1];   // [16384, 448]
    const void*  ix = d_in[2];                 // [16384] int32 or int64
    float* y = (float*)d_out;                  // [16384, 448]

    cudaFuncSetAttribute(compute_kernel,
                         cudaFuncAttributeMaxDynamicSharedMemorySize, SMEM_BYTES);

    prep_kernel<<<192 + XC_BLOCKS, PTHREADS>>>(W, x, ix);
    finish_kernel<<<NHB, PTHREADS>>>(ix);
    compute_kernel<<<GRID_COMPUTE, NTHREADS, SMEM_BYTES>>>(y);
}

// round 14
// speedup vs baseline: 1.0808x; 1.0808x over previous
#include <cuda_runtime.h>
#include <cuda_bf16.h>
#include <cstdint>

// Problem constants
#define BATCH    16384
#define IN_SIZE  448
#define OUT_SIZE 448
#define W_TOT    14336
#define NE       64
#define NB       64
#define NTHREADS 512
#define PTHREADS 256
#define NHB      (BATCH / PTHREADS)   // 64
#define MAX_TILES 384
#define GRID_COMPUTE 148

// B (W^T) image per element, padded row strides (odd*16 -> conflict-free)
#define B0_STR 208
#define B1_STR 144
#define B2_STR 80
#define OFF_B0H 0
#define OFF_B0L 19968
#define OFF_B1H 39936
#define OFF_B1L 49152
#define OFF_B2H 58368
#define OFF_B2L 60928
#define IMG_BYTES 63488

// Per-node blob (R10-verified layout), 2080 B
#define XN_BYTES 2080
#define XOFF_S0H 0
#define XOFF_S0L 208
#define XOFF_S1(m) (416 + 288 * (m))   // hi; lo at +144
#define XOFF_S2(m) (1280 + 160 * (m))  // hi; lo at +80

__device__ unsigned char g_Wimg[(size_t)NE * IMG_BYTES];
__device__ unsigned char g_xre[(size_t)BATCH * XN_BYTES];
__device__ int g_hist[NHB][NE];
__device__ int g_perm[BATCH];
__device__ int g_ntiles;
__device__ int g_tile_ctr;
__device__ int g_tile_e[MAX_TILES];
__device__ int g_tile_r0[MAX_TILES];
__device__ int g_tile_R[MAX_TILES];

__device__ __forceinline__ int get_idx(const void* p, int b, int is64) {
    if (is64) return (int)((const long long*)p)[b];
    return ((const int*)p)[b];
}
__device__ __forceinline__ int detect_is64(const void* idxp, int tid, int* s_flag) {
    if (tid < 32) {
        long long v = ((const long long*)idxp)[tid];
        unsigned ok = __ballot_sync(0xFFFFFFFFu, v >= 0 && v < 64);
        if (tid == 0) *s_flag = (ok == 0xFFFFFFFFu) ? 1 : 0;
    }
    __syncthreads();
    return *s_flag;
}
// Fast split: hi = truncate-to-bf16 (bit ops), lo = exact残差 rounded.
__device__ __forceinline__ uint32_t pk2fast(float a, float b, float* la, float* lb) {
    uint32_t ua = __float_as_uint(a), ub = __float_as_uint(b), h;
    asm("prmt.b32 %0, %1, %2, 0x7632;" : "=r"(h) : "r"(ua), "r"(ub));
    *la = a - __uint_as_float(ua & 0xFFFF0000u);
    *lb = b - __uint_as_float(ub & 0xFFFF0000u);
    return h;   // = bf16_trunc(a) | bf16_trunc(b)<<16
}
__device__ __forceinline__ uint32_t pklo(float la, float lb) {
    uint32_t r;
    asm("cvt.rn.bf16x2.f32 %0, %1, %2;" : "=r"(r) : "f"(lb), "f"(la));
    return r;   // bf16(la) | bf16(lb)<<16
}

// ---------------------------------------------------------------------------
// K0: fused prep. blocks [0,128): W images (2/element); [128,192): histogram;
// [192,192+2048): xconv (8 nodes/block, coalesced in/out)
// ---------------------------------------------------------------------------
#define XC_NODES 8
#define XC_BLOCKS (BATCH / XC_NODES)   // 2048
__global__ void prep_kernel(const float* __restrict__ W,
                            const float* __restrict__ x, const void* idxp) {
    __shared__ float sx[XC_NODES * IN_SIZE];
    __shared__ unsigned char sblob[XC_NODES * XN_BYTES];
    int tid = threadIdx.x;
    int blk = blockIdx.x;

    if (blk < 128) {
        int e = blk >> 1, hf = blk & 1;
        const float* We = W + (size_t)e * W_TOT;
        unsigned char* img = g_Wimg + (size_t)e * IMG_BYTES;
        for (int i = tid; i < 48 * 48; i += PTHREADS) {
            int o = 48 * hf + i / 48, k = 2 * (i % 48);
            float la, lb;
            uint32_t h = pk2fast(We[k * 96 + o], We[(k + 1) * 96 + o], &la, &lb);
            *(uint32_t*)(img + OFF_B0H + o * B0_STR + 2 * k) = h;
            *(uint32_t*)(img + OFF_B0L + o * B0_STR + 2 * k) = pklo(la, lb);
        }
        for (int i = tid; i < 32 * 32; i += PTHREADS) {
            int o = 32 * hf + (i >> 5), k = (i & 31) * 2;
            float la, lb;
            uint32_t h = pk2fast(We[9216 + k * 64 + o], We[9216 + (k + 1) * 64 + o], &la, &lb);
            *(uint32_t*)(img + OFF_B1H + o * B1_STR + 2 * k) = h;
            *(uint32_t*)(img + OFF_B1L + o * B1_STR + 2 * k) = pklo(la, lb);
        }
        for (int i = tid; i < 16 * 16; i += PTHREADS) {
            int o = 16 * hf + (i >> 4), k = (i & 15) * 2;
            float la, lb;
            uint32_t h = pk2fast(We[13312 + k * 32 + o], We[13312 + (k + 1) * 32 + o], &la, &lb);
            *(uint32_t*)(img + OFF_B2H + o * B2_STR + 2 * k) = h;
            *(uint32_t*)(img + OFF_B2L + o * B2_STR + 2 * k) = pklo(la, lb);
        }
    } else if (blk < 192) {
        __shared__ int h[NE];
        __shared__ int sflag;
        int b = blk - 128;
        if (tid < NE) h[tid] = 0;
        int is64 = detect_is64(idxp, tid, &sflag);
        int e = get_idx(idxp, b * PTHREADS + tid, is64);
        atomicAdd(&h[e], 1);
        __syncthreads();
        if (tid < NE) g_hist[b][tid] = h[tid];
    } else {
        int nb0 = (blk - 192) * XC_NODES;
        for (int i = tid; i < XC_NODES * 112; i += PTHREADS) {
            int n = i / 112, q = i - 112 * n;
            *(float4*)&sx[n * IN_SIZE + 4 * q] =
                *(const float4*)(x + (size_t)(nb0 + n) * IN_SIZE + 4 * q);
        }
        __syncthreads();
        for (int i = tid; i < XC_NODES * 224; i += PTHREADS) {
            int n = i / 224, r = i - 224 * n;
            const float* row = sx + n * IN_SIZE;
            unsigned char* ob = sblob + n * XN_BYTES;
            float a, b2;
            int hoff, loff, j;
            if (r < 48) {
                j = r;
                a = row[2 * j]; b2 = row[2 * j + 1];
                hoff = XOFF_S0H; loff = XOFF_S0L;
            } else if (r < 144) {
                int rr = r - 48, m = rr >> 5;
                j = rr & 31;
                int k = 2 * j;
                a = row[96 + 3 * k + m]; b2 = row[96 + 3 * (k + 1) + m];
                hoff = XOFF_S1(m); loff = hoff + 144;
            } else {
                int rr = r - 144, m = rr >> 4;
                j = rr & 15;
                int k = 2 * j;
                a = row[288 + 5 * k + m]; b2 = row[288 + 5 * (k + 1) + m];
                hoff = XOFF_S2(m); loff = hoff + 80;
            }
            float la, lb;
            uint32_t h = pk2fast(a, b2, &la, &lb);
            *(uint32_t*)(ob + hoff + 4 * j) = h;
            *(uint32_t*)(ob + loff + 4 * j) = pklo(la, lb);
        }
        __syncthreads();
        unsigned char* dst = g_xre + (size_t)nb0 * XN_BYTES;
        for (int i = tid; i < XC_NODES * XN_BYTES / 16; i += PTHREADS)
            *(float4*)(dst + 16 * i) = *(const float4*)(sblob + 16 * i);
    }
}

// ---------------------------------------------------------------------------
// K1: fused scan + scatter + tile-list (NB=64 tiles, full first)
// ---------------------------------------------------------------------------
__global__ void finish_kernel(const void* idxp) {
    __shared__ int preS[NE], totS[NE], offS[NE];
    __shared__ int sflag;
    int t = threadIdx.x, b = blockIdx.x;
    int is64 = detect_is64(idxp, t, &sflag);
    if (t < NE) {
        int pre = 0, tot = 0;
        #pragma unroll 8
        for (int bb = 0; bb < NHB; bb++) {
            int v = g_hist[bb][t];
            tot += v;
            if (bb < b) pre += v;
        }
        preS[t] = pre; totS[t] = tot;
    }
    __syncthreads();
    if (t == 0) {
        int s = 0;
        for (int e2 = 0; e2 < NE; e2++) { offS[e2] = s; s += totS[e2]; }
    }
    __syncthreads();
    int my = b * PTHREADS + t;
    int e = get_idx(idxp, my, is64);
    int rank = atomicAdd(&preS[e], 1);
    g_perm[offS[e] + rank] = my;

    if (b == 0 && t == 0) {
        int ts = 0;
        for (int e2 = 0; e2 < NE; e2++) {
            int c = totS[e2], o = offS[e2], nf = c >> 6;
            for (int i = 0; i < nf; i++) {
                g_tile_e[ts] = e2; g_tile_r0[ts] = o + (i << 6); g_tile_R[ts] = NB; ts++;
            }
        }
        for (int e2 = 0; e2 < NE; e2++) {
            int c = totS[e2], o = offS[e2], nf = c >> 6, rem = c & 63;
            if (rem) {
                g_tile_e[ts] = e2; g_tile_r0[ts] = o + (nf << 6); g_tile_R[ts] = rem; ts++;
            }
        }
        g_ntiles = ts;
        g_tile_ctr = 0;
    }
}

// ---------------------------------------------------------------------------
// Compute: ONE staging phase per tile, then all 9 GEMMs barrier-free.
// SMEM: ctrl 1024 | A: 64 nodes x 2096 B | B image 63488  = 198656
// ---------------------------------------------------------------------------
#define NODE_STR 2096
#define A_OFF  1024
#define BB_OFF (A_OFF + NB * NODE_STR)          // 135168
#define SMEM_BYTES (BB_OFF + IMG_BYTES)         // 198656

__device__ __forceinline__ uint32_t smem_u32(const void* p) {
    uint32_t a;
    asm("{ .reg .u64 t; cvta.to.shared.u64 t, %1; cvt.u32.u64 %0, t; }"
        : "=r"(a) : "l"(p));
    return a;
}
__device__ __forceinline__ void cpa16(uint32_t dst, const void* src) {
    asm volatile("cp.async.cg.shared.global [%0], [%1], 16;\n" :: "r"(dst), "l"(src));
}
__device__ __forceinline__ void cpa_commit_wait() {
    asm volatile("cp.async.commit_group;\ncp.async.wait_group 0;\n" ::: "memory");
}
__device__ __forceinline__ void ldm4(uint32_t* r, uint32_t a) {
    asm volatile("ldmatrix.sync.aligned.m8n8.x4.shared.b16 {%0,%1,%2,%3}, [%4];"
                 : "=r"(r[0]), "=r"(r[1]), "=r"(r[2]), "=r"(r[3]) : "r"(a));
}
__device__ __forceinline__ void ldm2(uint32_t* r, uint32_t a) {
    asm volatile("ldmatrix.sync.aligned.m8n8.x2.shared.b16 {%0,%1}, [%2];"
                 : "=r"(r[0]), "=r"(r[1]) : "r"(a));
}
__device__ __forceinline__ void mma16816(float* d, const uint32_t* a, const uint32_t* b) {
    asm volatile(
        "mma.sync.aligned.m16n8k16.row.col.f32.bf16.bf16.f32 "
        "{%0,%1,%2,%3}, {%4,%5,%6,%7}, {%8,%9}, {%0,%1,%2,%3};"
        : "+f"(d[0]), "+f"(d[1]), "+f"(d[2]), "+f"(d[3])
        : "r"(a[0]), "r"(a[1]), "r"(a[2]), "r"(a[3]), "r"(b[0]), "r"(b[1]));
}

__global__ void __launch_bounds__(NTHREADS)
compute_kernel(float* __restrict__ y)
{
    extern __shared__ unsigned char sm[];
    int* s_tile = (int*)(sm);
    int* s_node = (int*)(sm + 16);

    const int tid = threadIdx.x, lane = tid & 31, wid = tid >> 5;
    const int wr = wid & 3, wc = wid >> 2;        // 4 row stripes x 4 col groups
    const uint32_t base_u = smem_u32(sm);
    const uint32_t sA = base_u + A_OFF;
    const uint32_t sB = base_u + BB_OFF;
    const int nt = g_ntiles;

    // Verified ldmatrix lane components (rel_err 4.45e-6 across R10-R13)
    const int a_row = lane & 15;
    const int a_k16 = (lane >> 4) << 4;
    const int b_row = (lane & 7) + ((lane >> 4) << 3);
    const int b_k16 = ((lane >> 3) & 1) << 4;
    const int b2_row = lane & 7;
    const int b2_k16 = ((lane >> 3) & 1) << 4;

    for (int iter = 0; iter < MAX_TILES + 2; iter++) {
        if (tid == 0) *s_tile = atomicAdd(&g_tile_ctr, 1);
        __syncthreads();                          // also guards smem reuse
        const int t = *s_tile;
        if (t >= nt) break;
        const int e  = g_tile_e[t];
        const int r0 = g_tile_r0[t];
        const int R  = g_tile_R[t];
        if (tid < NB) s_node[tid] = g_perm[r0 + min(tid, R - 1)];
        __syncthreads();

        // ===== ONE staging phase: full B image + full A blobs =====
        {
            const unsigned char* bs = g_Wimg + (size_t)e * IMG_BYTES;
            for (int i = tid; i < IMG_BYTES / 16; i += NTHREADS)
                cpa16(sB + 16u * i, bs + 16 * i);
            for (int i = tid; i < R * 130; i += NTHREADS) {
                int nb = i / 130, j = i - 130 * nb;
                cpa16(sA + nb * NODE_STR + 16 * j,
                      g_xre + (size_t)s_node[nb] * XN_BYTES + 16 * j);
            }
            cpa_commit_wait();
        }
        __syncthreads();

        // ===== all 9 GEMMs, no barriers between =====
        const int arow16 = 16 * wr + a_row;       // this lane's A node row
        const int rA = 16 * wr + (lane >> 2), rB = rA + 8;
        const bool act = (16 * wr) < R;

        // ---- seg0: N=96, col group 24 (2 n8 x4 + 1 n8 x2), K=96
        if (act) {
            float c[3][4];
            #pragma unroll
            for (int j = 0; j < 3; j++)
                #pragma unroll
                for (int q = 0; q < 4; q++) c[j][q] = 0.f;
            const int cbase = 24 * wc;
            const uint32_t ah = sA + arow16 * NODE_STR + XOFF_S0H + a_k16;
            const uint32_t al = ah + 208;
            const uint32_t bh4 = sB + OFF_B0H + (cbase + b_row) * B0_STR + b_k16;
            const uint32_t bl4 = sB + OFF_B0L + (cbase + b_row) * B0_STR + b_k16;
            const uint32_t bh2 = sB + OFF_B0H + (cbase + 16 + b2_row) * B0_STR + b2_k16;
            const uint32_t bl2 = sB + OFF_B0L + (cbase + 16 + b2_row) * B0_STR + b2_k16;
            #pragma unroll
            for (int kk = 0; kk < 6; kk++) {
                const int ko = 32 * kk;
                uint32_t A[4], Al[4], Bh[4], Bl[4], Bh2[2], Bl2[2];
                ldm4(A, ah + ko);  ldm4(Al, al + ko);
                ldm4(Bh, bh4 + ko); ldm4(Bl, bl4 + ko);
                ldm2(Bh2, bh2 + ko); ldm2(Bl2, bl2 + ko);
                mma16816(c[0], A, Bh);     mma16816(c[0], Al, Bh);
                mma16816(c[0], A, Bl);
                mma16816(c[1], A, Bh + 2); mma16816(c[1], Al, Bh + 2);
                mma16816(c[1], A, Bl + 2);
                mma16816(c[2], A, Bh2);    mma16816(c[2], Al, Bh2);
                mma16816(c[2], A, Bl2);
            }
            int cb = cbase + 2 * (lane & 3);
            if (rA < R) {
                float* yp = y + (size_t)s_node[rA] * OUT_SIZE;
                #pragma unroll
                for (int j = 0; j < 3; j++)
                    *(float2*)(yp + cb + 8 * j) = make_float2(c[j][0], c[j][1]);
            }
            if (rB < R) {
                float* yp = y + (size_t)s_node[rB] * OUT_SIZE;
                #pragma unroll
                for (int j = 0; j < 3; j++)
                    *(float2*)(yp + cb + 8 * j) = make_float2(c[j][2], c[j][3]);
            }
        }

        // ---- seg1: m=0..2, N=64, col group 16, K=64
        if (act) {
            const uint32_t bh4 = sB + OFF_B1H + (16 * wc + b_row) * B1_STR + b_k16;
            const uint32_t bl4 = sB + OFF_B1L + (16 * wc + b_row) * B1_STR + b_k16;
            #pragma unroll
            for (int m = 0; m < 3; m++) {
                float c[2][4];
                #pragma unroll
                for (int jj = 0; jj < 2; jj++)
                    #pragma unroll
                    for (int q = 0; q < 4; q++) c[jj][q] = 0.f;
                const uint32_t ah = sA + arow16 * NODE_STR + XOFF_S1(m) + a_k16;
                const uint32_t al = ah + 144;
                #pragma unroll
                for (int kk = 0; kk < 4; kk++) {
                    const int ko = 32 * kk;
                    uint32_t A[4], Al[4], Bh[4], Bl[4];
                    ldm4(A, ah + ko);  ldm4(Al, al + ko);
                    ldm4(Bh, bh4 + ko); ldm4(Bl, bl4 + ko);
                    mma16816(c[0], A, Bh);     mma16816(c[0], Al, Bh);
                    mma16816(c[0], A, Bl);
                    mma16816(c[1], A, Bh + 2); mma16816(c[1], Al, Bh + 2);
                    mma16816(c[1], A, Bl + 2);
                }
                int cb = 16 * wc + 2 * (lane & 3);
                if (rA < R) {
                    float* yp = y + (size_t)s_node[rA] * OUT_SIZE + 96 + m;
                    #pragma unroll
                    for (int jj = 0; jj < 2; jj++) {
                        yp[3 * (cb + 8 * jj)] = c[jj][0];
                        yp[3 * (cb + 8 * jj + 1)] = c[jj][1];
                    }
                }
                if (rB < R) {
                    float* yp = y + (size_t)s_node[rB] * OUT_SIZE + 96 + m;
                    #pragma unroll
                    for (int jj = 0; jj < 2; jj++) {
                        yp[3 * (cb + 8 * jj)] = c[jj][2];
                        yp[3 * (cb + 8 * jj + 1)] = c[jj][3];
                    }
                }
            }
        }

        // ---- seg2: m=0..4, N=32, col group 8 (1 n8 via x2), K=32
        if (act) {
            const uint32_t bh2 = sB + OFF_B2H + (8 * wc + b2_row) * B2_STR + b2_k16;
            const uint32_t bl2 = sB + OFF_B2L + (8 * wc + b2_row) * B2_STR + b2_k16;
            #pragma unroll
            for (int m = 0; m < 5; m++) {
                float c[4];
                c[0] = c[1] = c[2] = c[3] = 0.f;
                const uint32_t ah = sA + arow16 * NODE_STR + XOFF_S2(m) + a_k16;
                const uint32_t al = ah + 80;
                #pragma unroll
                for (int kk = 0; kk < 2; kk++) {
                    const int ko = 32 * kk;
                    uint32_t A[4], Al[4], Bh2[2], Bl2[2];
                    ldm4(A, ah + ko);  ldm4(Al, al + ko);
                    ldm2(Bh2, bh2 + ko); ldm2(Bl2, bl2 + ko);
                    mma16816(c, A, Bh2);
                    mma16816(c, Al, Bh2);
                    mma16816(c, A, Bl2);
                }
                int cb = 8 * wc + 2 * (lane & 3);
                if (rA < R) {
                    float* yp = y + (size_t)s_node[rA] * OUT_SIZE + 288 + m;
                    yp[5 * cb] = c[0];
                    yp[5 * (cb + 1)] = c[1];
                }
                if (rB < R) {
                    float* yp = y + (size_t)s_node[rB] * OUT_SIZE + 288 + m;
                    yp[5 * cb] = c[2];
                    yp[5 * (cb + 1)] = c[3];
                }
            }
        }
        // loop-top __syncthreads() guards smem reuse for the next tile
    }
}

// ---------------------------------------------------------------------------
// Launch (3 kernels)
// ---------------------------------------------------------------------------
extern "C" void kernel_launch(void* const* d_in, const int* in_sizes, int n_in,
                              void* d_out, int out_size)
{
    const float* W  = (const float*)d_in[0];   // [64, 14336]
    const float* x  = (const float*)d_in[1];   // [16384, 448]
    const void*  ix = d_in[2];                 // [16384] int32 or int64
    float* y = (float*)d_out;                  // [16384, 448]

    cudaFuncSetAttribute(compute_kernel,
                         cudaFuncAttributeMaxDynamicSharedMemorySize, SMEM_BYTES);

    prep_kernel<<<192 + XC_BLOCKS, PTHREADS>>>(W, x, ix);
    finish_kernel<<<NHB, PTHREADS>>>(ix);
    compute_kernel<<<GRID_COMPUTE, NTHREADS, SMEM_BYTES>>>(y);
}